// round 1
// baseline (speedup 1.0000x reference)
#include <cuda_runtime.h>
#include <math.h>

// Problem constants
#define BATCH   65536
#define SDIM    256
#define AGENTS  8
#define NACT    16
#define KKER    10
#define HDIM    64
#define ADIM    128          // AGENTS*NACT
#define DDIM    384          // SDIM + ADIM

// Tiling
#define TB       64          // batch rows per CTA
#define NTHREADS 256
#define STRIDE   68          // padded row stride (floats) for [d][i] smem tiles
#define WCHUNK   256         // W1 staging chunk along in-dim

// Shared memory layout (float offsets)
#define XS_OFF   0                       // [384][STRIDE] input tile (states||actions), transposed
#define WS_OFF   (XS_OFF + DDIM*STRIDE)  // [256][STRIDE] weight chunk, transposed; also W3 vector
#define H1_OFF   (WS_OFF + WCHUNK*STRIDE)// [64][STRIDE] hidden 1
#define H2_OFF   (H1_OFF + HDIM*STRIDE)  // [64][STRIDE] hidden 2
#define KEY_OFF  (H2_OFF + HDIM*STRIDE)  // [64]
#define AG_OFF   (KEY_OFF + TB)          // [64][8]
#define ACC_OFF  (AG_OFF + TB*AGENTS)    // [64][8]
#define SMEM_FLOATS (ACC_OFF + TB*AGENTS)
// = 384*68 + 256*68 + 64*68 + 64*68 + 64 + 512 + 512 = 53312 floats = 213248 B

__device__ __forceinline__ float sigmoidf_(float x) {
    return 1.0f / (1.0f + expf(-x));
}

// GEMM: out[i=0..63][j=0..63] = sum_d xs[d][i] * Wg[j][d]
// xs is smem transposed [IN][STRIDE]; Wg is global row-major [64][IN].
// Each thread computes a 4x4 micro-tile. acc is zeroed here.
__device__ __forceinline__ void gemm64(
    const float* __restrict__ xs,
    const float* __restrict__ wg,
    float* __restrict__ ws,
    float acc[4][4], int IN, int tid)
{
    const int tx = (tid & 15) << 2;   // i0
    const int ty = (tid >> 4) << 2;   // j0

    #pragma unroll
    for (int ii = 0; ii < 4; ii++)
        #pragma unroll
        for (int jj = 0; jj < 4; jj++)
            acc[ii][jj] = 0.0f;

    for (int c0 = 0; c0 < IN; c0 += WCHUNK) {
        const int CL = (IN - c0) < WCHUNK ? (IN - c0) : WCHUNK;   // 256/128/64, pow2
        const int cshift = (CL == 256) ? 8 : (CL == 128 ? 7 : 6);

        __syncthreads();   // prior consumers of ws / producers of xs done
        // stage W chunk transposed: ws[d][h] = wg[h][c0+d]; global reads coalesced over d
        for (int idx = tid; idx < (CL << 6); idx += NTHREADS) {
            int dd = idx & (CL - 1);
            int hh = idx >> cshift;
            ws[dd * STRIDE + hh] = __ldg(wg + hh * IN + c0 + dd);
        }
        __syncthreads();

        const float* xp = xs + c0 * STRIDE;
        #pragma unroll 4
        for (int dd = 0; dd < CL; dd++) {
            float4 a = *reinterpret_cast<const float4*>(xp + dd * STRIDE + tx);
            float4 b = *reinterpret_cast<const float4*>(ws + dd * STRIDE + ty);
            acc[0][0] += a.x * b.x; acc[0][1] += a.x * b.y; acc[0][2] += a.x * b.z; acc[0][3] += a.x * b.w;
            acc[1][0] += a.y * b.x; acc[1][1] += a.y * b.y; acc[1][2] += a.y * b.z; acc[1][3] += a.y * b.w;
            acc[2][0] += a.z * b.x; acc[2][1] += a.z * b.y; acc[2][2] += a.z * b.z; acc[2][3] += a.z * b.w;
            acc[3][0] += a.w * b.x; acc[3][1] += a.w * b.y; acc[3][2] += a.w * b.z; acc[3][3] += a.w * b.w;
        }
    }
}

// Epilogue: h[j][i] = relu(acc[i][j] + bias[j]) into smem [64][STRIDE]
__device__ __forceinline__ void epi_relu(
    const float acc[4][4], const float* __restrict__ bias,
    float* __restrict__ hdst, int tid)
{
    const int tx = (tid & 15) << 2;
    const int ty = (tid >> 4) << 2;
    #pragma unroll
    for (int jj = 0; jj < 4; jj++) {
        float bj = __ldg(bias + ty + jj);
        #pragma unroll
        for (int ii = 0; ii < 4; ii++) {
            float v = acc[ii][jj] + bj;
            hdst[(ty + jj) * STRIDE + tx + ii] = v > 0.0f ? v : 0.0f;
        }
    }
}

__global__ void __launch_bounds__(NTHREADS, 1)
qplex_si_kernel(
    const float* __restrict__ states,
    const float* __restrict__ actions,
    const float* __restrict__ kW1, const float* __restrict__ kb1,
    const float* __restrict__ kW2, const float* __restrict__ kb2,
    const float* __restrict__ kW3, const float* __restrict__ kb3,
    const float* __restrict__ aW1, const float* __restrict__ ab1,
    const float* __restrict__ aW2, const float* __restrict__ ab2,
    const float* __restrict__ aW3, const float* __restrict__ ab3,
    const float* __restrict__ cW1, const float* __restrict__ cb1,
    const float* __restrict__ cW2, const float* __restrict__ cb2,
    const float* __restrict__ cW3, const float* __restrict__ cb3,
    float* __restrict__ out)
{
    extern __shared__ float sm[];
    float* xs   = sm + XS_OFF;
    float* ws   = sm + WS_OFF;
    float* h1   = sm + H1_OFF;
    float* h2   = sm + H2_OFF;
    float* keyb = sm + KEY_OFF;
    float* agb  = sm + AG_OFF;
    float* accb = sm + ACC_OFF;

    const int tid = threadIdx.x;
    const int b0  = blockIdx.x * TB;

    // Stage input tile transposed: xs[d][i]. d<256 from states, d>=256 from actions.
    for (int idx = tid; idx < TB * SDIM; idx += NTHREADS) {          // 16384
        int i  = idx >> 8;
        int dd = idx & 255;
        xs[dd * STRIDE + i] = states[(size_t)(b0 + i) * SDIM + dd];
    }
    for (int idx = tid; idx < TB * ADIM; idx += NTHREADS) {          // 8192
        int i  = idx >> 7;
        int dd = idx & 127;
        xs[(SDIM + dd) * STRIDE + i] = actions[(size_t)(b0 + i) * ADIM + dd];
    }
    for (int idx = tid; idx < TB * AGENTS; idx += NTHREADS)
        accb[idx] = 0.0f;
    // gemm64's leading __syncthreads covers these writes.

    float acc[4][4];
    const int i_  = tid & 63;
    const int og_ = (tid >> 6) << 1;   // 0,2,4,6

    for (int k = 0; k < KKER; k++) {
        // ---------------- KEY net: states -> 64 -> 64 -> 1, |.|+1e-10 -------------
        gemm64(xs, kW1 + k * HDIM * SDIM, ws, acc, SDIM, tid);
        epi_relu(acc, kb1 + k * HDIM, h1, tid);
        gemm64(h1, kW2 + k * HDIM * HDIM, ws, acc, HDIM, tid);
        epi_relu(acc, kb2 + k * HDIM, h2, tid);
        __syncthreads();
        if (tid < HDIM) ws[tid] = __ldg(kW3 + k * HDIM + tid);
        __syncthreads();
        if (tid < TB) {
            float s = __ldg(kb3 + k);
            #pragma unroll 8
            for (int h = 0; h < HDIM; h++)
                s += h2[h * STRIDE + tid] * ws[h];
            keyb[tid] = fabsf(s) + 1e-10f;
        }

        // ---------------- AGENTS net: states -> 64 -> 64 -> 8, sigmoid ------------
        gemm64(xs, aW1 + k * HDIM * SDIM, ws, acc, SDIM, tid);
        epi_relu(acc, ab1 + k * HDIM, h1, tid);
        gemm64(h1, aW2 + k * HDIM * HDIM, ws, acc, HDIM, tid);
        epi_relu(acc, ab2 + k * HDIM, h2, tid);
        __syncthreads();
        for (int idx = tid; idx < AGENTS * HDIM; idx += NTHREADS)
            ws[idx] = __ldg(aW3 + k * AGENTS * HDIM + idx);
        __syncthreads();
        {
            float s0 = __ldg(ab3 + k * AGENTS + og_);
            float s1 = __ldg(ab3 + k * AGENTS + og_ + 1);
            const float* w0 = ws + og_ * HDIM;
            const float* w1 = w0 + HDIM;
            #pragma unroll 8
            for (int h = 0; h < HDIM; h++) {
                float x = h2[h * STRIDE + i_];
                s0 += x * w0[h];
                s1 += x * w1[h];
            }
            agb[i_ * AGENTS + og_]     = sigmoidf_(s0);
            agb[i_ * AGENTS + og_ + 1] = sigmoidf_(s1);
        }

        // ---------------- ACTION net: data(384) -> 64 -> 64 -> 8, sigmoid ---------
        gemm64(xs, cW1 + k * HDIM * DDIM, ws, acc, DDIM, tid);
        epi_relu(acc, cb1 + k * HDIM, h1, tid);
        gemm64(h1, cW2 + k * HDIM * HDIM, ws, acc, HDIM, tid);
        epi_relu(acc, cb2 + k * HDIM, h2, tid);
        __syncthreads();
        for (int idx = tid; idx < AGENTS * HDIM; idx += NTHREADS)
            ws[idx] = __ldg(cW3 + k * AGENTS * HDIM + idx);
        __syncthreads();
        {
            float s0 = __ldg(cb3 + k * AGENTS + og_);
            float s1 = __ldg(cb3 + k * AGENTS + og_ + 1);
            const float* w0 = ws + og_ * HDIM;
            const float* w1 = w0 + HDIM;
            #pragma unroll 8
            for (int h = 0; h < HDIM; h++) {
                float x = h2[h * STRIDE + i_];
                s0 += x * w0[h];
                s1 += x * w1[h];
            }
            float kv = keyb[i_];
            accb[i_ * AGENTS + og_]     += kv * agb[i_ * AGENTS + og_]     * sigmoidf_(s0);
            accb[i_ * AGENTS + og_ + 1] += kv * agb[i_ * AGENTS + og_ + 1] * sigmoidf_(s1);
        }
        // next iteration's gemm64 leading __syncthreads is the k-boundary barrier
    }

    __syncthreads();
    for (int idx = tid; idx < TB * AGENTS; idx += NTHREADS)
        out[(size_t)b0 * AGENTS + idx] = accb[idx];
}

extern "C" void kernel_launch(void* const* d_in, const int* in_sizes, int n_in,
                              void* d_out, int out_size)
{
    const float* states  = (const float*)d_in[0];
    const float* actions = (const float*)d_in[1];
    const float* kW1 = (const float*)d_in[2];
    const float* kb1 = (const float*)d_in[3];
    const float* kW2 = (const float*)d_in[4];
    const float* kb2 = (const float*)d_in[5];
    const float* kW3 = (const float*)d_in[6];
    const float* kb3 = (const float*)d_in[7];
    const float* aW1 = (const float*)d_in[8];
    const float* ab1 = (const float*)d_in[9];
    const float* aW2 = (const float*)d_in[10];
    const float* ab2 = (const float*)d_in[11];
    const float* aW3 = (const float*)d_in[12];
    const float* ab3 = (const float*)d_in[13];
    const float* cW1 = (const float*)d_in[14];
    const float* cb1 = (const float*)d_in[15];
    const float* cW2 = (const float*)d_in[16];
    const float* cb2 = (const float*)d_in[17];
    const float* cW3 = (const float*)d_in[18];
    const float* cb3 = (const float*)d_in[19];
    float* out = (float*)d_out;

    const size_t smem_bytes = (size_t)SMEM_FLOATS * sizeof(float);  // 213248
    cudaFuncSetAttribute(qplex_si_kernel,
                         cudaFuncAttributeMaxDynamicSharedMemorySize,
                         (int)smem_bytes);

    qplex_si_kernel<<<BATCH / TB, NTHREADS, smem_bytes>>>(
        states, actions,
        kW1, kb1, kW2, kb2, kW3, kb3,
        aW1, ab1, aW2, ab2, aW3, ab3,
        cW1, cb1, cW2, cb2, cW3, cb3,
        out);
}